// round 15
// baseline (speedup 1.0000x reference)
#include <cuda_runtime.h>
#include <cstdint>
#include <math.h>

#define BSD 8388608
#define BSF 33554432

__device__ float g_xn[BSD];
__device__ float g_qkv[25165824];
__device__ float g_attn[BSD];
__device__ float g_x1[BSD];
__device__ float g_h[BSF];
__device__ float g_wqkvt[12582912];
__device__ float g_wot[4194304];
__device__ float g_wint[16777216];
__device__ float g_woutt[16777216];
__device__ float g_bqkv[6144];

__device__ __forceinline__ float to_tf32(float x) {
    float r; asm("cvt.rna.tf32.f32 %0, %1;" : "=f"(r) : "f"(x)); return r;
}
__device__ __forceinline__ uint32_t smem_u32(const void* p) {
    uint32_t a;
    asm("{ .reg .u64 t; cvta.to.shared.u64 t, %1; cvt.u32.u64 %0, t; }"
        : "=r"(a) : "l"(p));
    return a;
}
__device__ __forceinline__ void cp16(uint32_t s, const void* g) {
    asm volatile("cp.async.cg.shared.global [%0], [%1], 16;" :: "r"(s), "l"(g));
}
__device__ __forceinline__ void mma8(float* d, const uint32_t* a, const uint32_t* b) {
    asm volatile(
        "mma.sync.aligned.m16n8k8.row.col.f32.tf32.tf32.f32 "
        "{%0,%1,%2,%3}, {%4,%5,%6,%7}, {%8,%9}, {%0,%1,%2,%3};\n"
        : "+f"(d[0]), "+f"(d[1]), "+f"(d[2]), "+f"(d[3])
        : "r"(a[0]), "r"(a[1]), "r"(a[2]), "r"(a[3]), "r"(b[0]), "r"(b[1]));
}
__device__ __forceinline__ float gelu_f(float v) {
    return 0.5f * v * (1.0f + erff(v * 0.70710678118654752f));
}
__device__ __forceinline__ float fexp(float x) {
    float y = x * 1.4426950408889634f;
    y = fmaxf(y, -126.0f);
    const float magic = 12582912.0f;
    const float z = y + magic;
    const int   n = __float_as_int(z) - 0x4B400000;
    const float f = y - (z - magic);
    float r = 0.0013333558f;
    r = fmaf(r, f, 0.0096181291f);
    r = fmaf(r, f, 0.0555041087f);
    r = fmaf(r, f, 0.2402265069f);
    r = fmaf(r, f, 0.6931471806f);
    r = fmaf(r, f, 1.0f);
    return __int_as_float(__float_as_int(r) + (n << 23));
}
// t4-major k-permutation within 32-k tile: logical x -> (l&3)*8 + ks*2 + (l>>2)
__device__ __forceinline__ int permc32(int x) {
    const int l = x & 7;
    return ((l & 3) << 3) | (((x >> 3) & 3) << 1) | (l >> 2);
}
__device__ __forceinline__ int poff(int l, int ks) {
    return ((l & 3) << 3) | (ks << 1) | (l >> 2);
}

// ---------------- weight prep (t4-major) -----------------------------------
__device__ void tp_tile(const float* __restrict__ src, float* __restrict__ dst,
                        int K, int N, int t)
{
    __shared__ float tbuf[32][33];
    const int tn = N >> 5;
    const int n0 = (t % tn) << 5, k0 = (t / tn) << 5;
    const int x = threadIdx.x & 31, y = threadIdx.x >> 5;
    #pragma unroll
    for (int i = 0; i < 32; i += 8)
        tbuf[y + i][x] = src[(size_t)(k0 + y + i) * N + n0 + x];
    __syncthreads();
    const int kp = k0 + permc32(x);
    #pragma unroll
    for (int i = 0; i < 32; i += 8)
        dst[(size_t)(n0 + y + i) * K + kp] = to_tf32(tbuf[x][y + i]);
}

__global__ __launch_bounds__(256) void prep_a(
    const float* __restrict__ wq, const float* __restrict__ wk,
    const float* __restrict__ wv, const float* __restrict__ bq,
    const float* __restrict__ bk, const float* __restrict__ bv)
{
    const int blk = blockIdx.x;
    if (blk < 12288) {
        const int w = blk >> 12, t = blk & 4095;
        const float* src = (w == 0) ? wq : (w == 1) ? wk : wv;
        tp_tile(src, g_wqkvt + (size_t)w * 4194304, 2048, 2048, t);
    } else {
        const int idx = ((blk - 12288) << 8) + threadIdx.x;
        if (idx < 6144) {
            const int sel = idx >> 11;
            const float* b = (sel == 0) ? bq : (sel == 1) ? bk : bv;
            g_bqkv[idx] = b[idx & 2047];
        }
    }
}

__global__ __launch_bounds__(256) void prep_b(
    const float* __restrict__ wo, const float* __restrict__ w_in,
    const float* __restrict__ w_out)
{
    const int blk = blockIdx.x;
    if (blk < 4096)        tp_tile(wo,    g_wot,   2048, 2048, blk);
    else if (blk < 20480)  tp_tile(w_in,  g_wint,  2048, 8192, blk - 4096);
    else                   tp_tile(w_out, g_woutt, 8192, 2048, blk - 20480);
}

// ---------------- block reduce + LayerNorm (t4-major out) ------------------
__device__ __forceinline__ float block_sum256(float v) {
    __shared__ float red[8];
    #pragma unroll
    for (int o = 16; o; o >>= 1) v += __shfl_xor_sync(0xffffffffu, v, o);
    const int w = threadIdx.x >> 5, l = threadIdx.x & 31;
    __syncthreads();
    if (l == 0) red[w] = v;
    __syncthreads();
    float t = red[l & 7];
    t += __shfl_xor_sync(0xffffffffu, t, 1);
    t += __shfl_xor_sync(0xffffffffu, t, 2);
    t += __shfl_xor_sync(0xffffffffu, t, 4);
    return t;
}

__global__ __launch_bounds__(256) void ln_kernel(
    const float* __restrict__ x, const float* __restrict__ gw,
    const float* __restrict__ bw, float* __restrict__ y)
{
    const size_t base = (size_t)blockIdx.x * 2048;
    const int c0 = threadIdx.x << 3;
    const float4 v0 = *(const float4*)&x[base + c0];
    const float4 v1 = *(const float4*)&x[base + c0 + 4];

    float s = v0.x + v0.y + v0.z + v0.w + v1.x + v1.y + v1.z + v1.w;
    const float mean = block_sum256(s) * (1.0f / 2048.0f);

    float d[8];
    d[0] = v0.x - mean; d[1] = v0.y - mean; d[2] = v0.z - mean; d[3] = v0.w - mean;
    d[4] = v1.x - mean; d[5] = v1.y - mean; d[6] = v1.z - mean; d[7] = v1.w - mean;
    float q = 0.f;
    #pragma unroll
    for (int i = 0; i < 8; i++) q += d[i] * d[i];
    const float var = block_sum256(q) * (1.0f / 2048.0f);
    const float rs = rsqrtf(var + 1e-5f);

    const float4 g0 = *(const float4*)&gw[c0];
    const float4 g1 = *(const float4*)&gw[c0 + 4];
    const float4 b0 = *(const float4*)&bw[c0];
    const float4 b1 = *(const float4*)&bw[c0 + 4];
    const float ga[8] = {g0.x, g0.y, g0.z, g0.w, g1.x, g1.y, g1.z, g1.w};
    const float ba[8] = {b0.x, b0.y, b0.z, b0.w, b1.x, b1.y, b1.z, b1.w};

    float o[8];
    #pragma unroll
    for (int i = 0; i < 8; i++) o[i] = to_tf32(d[i] * rs * ga[i] + ba[i]);

    // t4-major: logical (i, i+4) -> phys base32 + i*8 + ks*2 + {0,1}
    const int ks = threadIdx.x & 3;
    const size_t b32 = base + ((threadIdx.x >> 2) << 5);
    #pragma unroll
    for (int i = 0; i < 4; i++)
        *(float2*)&y[b32 + (i << 3) + (ks << 1)] = make_float2(o[i], o[i + 4]);
}

// ---------------- TF32 GEMM: LDS.128 frags, pad-36, dist-8 ordering --------
// Stage: A 128x36f + B 128x36f = 36864B; 3 stages = 110592B.
#define GSMEM 110592

template<int ACT, int HASRES, int RND, int PERMC>
__global__ __launch_bounds__(256, 2) void gemm_cp(
    const float* __restrict__ A, const float* __restrict__ Wt,
    const float* __restrict__ bias, const float* __restrict__ res,
    float* __restrict__ C, int M, int N, int K)
{
    extern __shared__ float sm[];
    const uint32_t sb = smem_u32(sm);
    const int tid = threadIdx.x;
    const int warp = tid >> 5, lane = tid & 31;
    const int wm = warp >> 1, wn = warp & 1;
    const int g = lane >> 2, t4 = lane & 3;
    const int bm = blockIdx.y << 7, bn = blockIdx.x << 7;

    const int KT = K >> 5;

    // copy geometry: pad-36 rows, pointer-increment
    const int r0 = tid >> 3, cc = (tid & 7) << 2;
    const uint32_t dA0 = (uint32_t)(r0 * 144 + ((tid & 7) << 4));
    const float* gA = A  + (size_t)(bm + r0) * K + cc;
    const float* gB = Wt + (size_t)(bn + r0) * K + cc;
    const size_t gstep = (size_t)K << 5;   // 32 rows

    float acc[2][8][4];
    #pragma unroll
    for (int a = 0; a < 2; a++)
        #pragma unroll
        for (int b2 = 0; b2 < 8; b2++)
            #pragma unroll
            for (int c = 0; c < 4; c++) acc[a][b2][c] = 0.f;

    auto issue = [&](int s) {
        const uint32_t st = sb + (uint32_t)s * 36864u;
        const float* ga = gA; const float* gb = gB;
        #pragma unroll
        for (int i = 0; i < 4; i++) {
            cp16(st + dA0 + i * 4608u, ga);
            cp16(st + 18432u + dA0 + i * 4608u, gb);
            ga += gstep; gb += gstep;
        }
        gA += 32; gB += 32;
        asm volatile("cp.async.commit_group;" ::: "memory");
    };

    issue(0);
    issue(1);

    const int arow0 = ((wm << 5) + g) * 36 + (t4 << 3);
    const int brow0 = ((wn << 6) + g) * 36 + (t4 << 3);

    int s = 0;
    for (int kt = 0; kt < KT; kt++) {
        if (kt + 1 < KT) asm volatile("cp.async.wait_group 1;" ::: "memory");
        else             asm volatile("cp.async.wait_group 0;" ::: "memory");
        __syncthreads();
        if (kt + 2 < KT) {
            int ns = s + 2; if (ns >= 3) ns -= 3;
            issue(ns);
        }
        const float* As = sm + s * 9216;
        const float* Bs = As + 4608;

        #pragma unroll
        for (int P = 0; P < 2; P++) {
            const float4 A00 = *(const float4*)&As[arow0 + (P << 2)];
            const float4 A01 = *(const float4*)&As[arow0 + 288 + (P << 2)];
            const float4 A10 = *(const float4*)&As[arow0 + 576 + (P << 2)];
            const float4 A11 = *(const float4*)&As[arow0 + 864 + (P << 2)];
            uint32_t afe0[4] = {__float_as_uint(A00.x), __float_as_uint(A01.x),
                                __float_as_uint(A00.y), __float_as_uint(A01.y)};
            uint32_t afe1[4] = {__float_as_uint(A10.x), __float_as_uint(A11.x),
                                __float_as_uint(A10.y), __float_as_uint(A11.y)};
            uint32_t afo0[4] = {__float_as_uint(A00.z), __float_as_uint(A01.z),
                                __float_as_uint(A00.w), __float_as_uint(A01.w)};
            uint32_t afo1[4] = {__float_as_uint(A10.z), __float_as_uint(A11.z),
                                __float_as_uint(A10.w), __float_as_uint(A11.w)};
            #pragma unroll
            for (int nh = 0; nh < 2; nh++) {
                float4 Bv[4];
                #pragma unroll
                for (int j = 0; j < 4; j++)
                    Bv[j] = *(const float4*)&Bs[brow0 + ((nh << 2) + j) * 288 + (P << 2)];
                // even sub-k across all 4 ni
                #pragma unroll
                for (int j = 0; j < 4; j++) {
                    uint32_t bf[2] = {__float_as_uint(Bv[j].x), __float_as_uint(Bv[j].y)};
                    mma8(acc[0][(nh << 2) + j], afe0, bf);
                    mma8(acc[1][(nh << 2) + j], afe1, bf);
                }
                // odd sub-k across all 4 ni (distance 8 from even writes)
                #pragma unroll
                for (int j = 0; j < 4; j++) {
                    uint32_t bf[2] = {__float_as_uint(Bv[j].z), __float_as_uint(Bv[j].w)};
                    mma8(acc[0][(nh << 2) + j], afo0, bf);
                    mma8(acc[1][(nh << 2) + j], afo1, bf);
                }
            }
        }
        if (++s == 3) s = 0;
    }

    // epilogue
    #pragma unroll
    for (int mi = 0; mi < 2; mi++) {
        const int row0 = bm + (wm << 5) + (mi << 4) + g;
        #pragma unroll
        for (int ni = 0; ni < 8; ni++) {
            const int base = bn + (wn << 6) + (ni << 3);
            const int lcol = base + (t4 << 1);
            const float b0 = bias[lcol], b1 = bias[lcol + 1];
            float v00 = acc[mi][ni][0] + b0, v01 = acc[mi][ni][1] + b1;
            float v10 = acc[mi][ni][2] + b0, v11 = acc[mi][ni][3] + b1;
            const size_t i0 = (size_t)row0 * N + lcol;
            const size_t i1 = i0 + (size_t)8 * N;
            if (HASRES) {
                v00 += res[i0]; v01 += res[i0 + 1];
                v10 += res[i1]; v11 += res[i1 + 1];
            }
            if (ACT == 1) {
                v00 = to_tf32(gelu_f(v00)); v01 = to_tf32(gelu_f(v01));
                v10 = to_tf32(gelu_f(v10)); v11 = to_tf32(gelu_f(v11));
            } else if (RND) {
                v00 = to_tf32(v00); v01 = to_tf32(v01);
                v10 = to_tf32(v10); v11 = to_tf32(v11);
            }
            if (PERMC) {
                const int ks = ni & 3;
                const int p0 = poff(t4 << 1, ks);   // poff(2t4+1,ks) = p0+8
                const size_t r0i = (size_t)row0 * N + (base & ~31) + p0;
                const size_t r1i = r0i + (size_t)8 * N;
                C[r0i] = v00; C[r0i + 8] = v01;
                C[r1i] = v10; C[r1i + 8] = v11;
            } else {
                *(float2*)&C[i0] = make_float2(v00, v01);
                *(float2*)&C[i1] = make_float2(v10, v11);
            }
        }
    }
}

// ---------------- causal flash attention: q-tile 128, 512 threads ----------
#define FSMEM 171520

__global__ __launch_bounds__(512, 1) void flash_kernel(
    const float* __restrict__ QKV, float* __restrict__ O)
{
    extern __shared__ float smf[];
    float* Qs   = smf;                 // [128][132]
    float* Ks   = smf + 16896;         // [64][132]
    float* Vs   = smf + 25344;         // [64][132]
    float* Ss   = smf + 33792;         // [128][68]
    float* mrow = smf + 42496;
    float* lrow = smf + 42624;
    float* arow = smf + 42752;

    const int tid = threadIdx.x;
    const int warp = tid >> 5, lane = tid & 31;
    const int g = lane >> 2, t4 = lane & 3;
    const int wm = warp >> 2, wn = warp & 3;
    const int b = blockIdx.y >> 4, h = blockIdx.y & 15;
    const int qi = (int)gridDim.x - 1 - (int)blockIdx.x;   // heaviest first
    const int q0 = qi << 7;
    const size_t qbase = (size_t)b * 2048 * 6144 + (size_t)h * 128;
    const float* Qg = QKV + qbase;
    const float* Kg = QKV + qbase + 2048;
    const float* Vg = QKV + qbase + 4096;
    float*       Og = O + ((size_t)b * 2048) * 2048 + (size_t)h * 128;

    #pragma unroll
    for (int rr = 0; rr < 8; rr++) {
        const int f4 = tid + (rr << 9);
        const int row = f4 >> 5, c4 = f4 & 31;
        *(float4*)&Qs[row * 132 + (c4 << 2)] =
            *(const float4*)&Qg[(size_t)(q0 + row) * 6144 + (c4 << 2)];
    }
    if (tid < 128) { mrow[tid] = -1e30f; lrow[tid] = 0.f; }

    float o[2][4][4];
    #pragma unroll
    for (int mi = 0; mi < 2; mi++)
        #pragma unroll
        for (int ni = 0; ni < 4; ni++)
            #pragma unroll
            for (int c = 0; c < 4; c++) o[mi][ni][c] = 0.f;

    const int ntile = (qi << 1) + 2;
    for (int kt = 0; kt < ntile; kt++) {
        const int k0 = kt << 6;
        __syncthreads();
        #pragma unroll
        for (int rr = 0; rr < 4; rr++) {
            const int f4 = tid + (rr << 9);
            const int row = f4 >> 5, c4 = f4 & 31;
            *(float4*)&Ks[row * 132 + (c4 << 2)] =
                *(const float4*)&Kg[(size_t)(k0 + row) * 6144 + (c4 << 2)];
            *(float4*)&Vs[row * 132 + (c4 << 2)] =
                *(const float4*)&Vg[(size_t)(k0 + row) * 6144 + (c4 << 2)];
        }
        __syncthreads();

        // S[128,64] = Q K^T (warp tile 32q x 16n)
        {
            float sacc[2][2][4];
            #pragma unroll
            for (int mi = 0; mi < 2; mi++)
                #pragma unroll
                for (int ni = 0; ni < 2; ni++)
                    #pragma unroll
                    for (int c = 0; c < 4; c++) sacc[mi][ni][c] = 0.f;
            const int m0 = wm << 5, nb = wn << 4;
            #pragma unroll
            for (int kk = 0; kk < 16; kk++) {
                const int kb = kk << 3;
                uint32_t af[2][4];
                #pragma unroll
                for (int mi = 0; mi < 2; mi++) {
                    const int mr = m0 + (mi << 4);
                    af[mi][0] = __float_as_uint(Qs[(mr + g    ) * 132 + kb + t4    ]);
                    af[mi][1] = __float_as_uint(Qs[(mr + g + 8) * 132 + kb + t4    ]);
                    af[mi][2] = __float_as_uint(Qs[(mr + g    ) * 132 + kb + t4 + 4]);
                    af[mi][3] = __float_as_uint(Qs[(mr + g + 8) * 132 + kb + t4 + 4]);
                }
                #pragma unroll
                for (int ni = 0; ni < 2; ni++) {
                    const int n = nb + (ni << 3) + g;
                    uint32_t bf[2];
                    bf[0] = __float_as_uint(Ks[n * 132 + kb + t4    ]);
                    bf[1] = __float_as_uint(Ks[n * 132 + kb + t4 + 4]);
                    mma8(sacc[0][ni], af[0], bf);
                    mma8(sacc[1][ni], af[1], bf);
                }
            }
            #pragma unroll
            for (int mi = 0; mi < 2; mi++) {
                const int r0 = m0 + (mi << 4) + g, r1 = r0 + 8;
                #pragma unroll
                for (int ni = 0; ni < 2; ni++) {
                    const int col = nb + (ni << 3) + (t4 << 1);
                    float v00 = sacc[mi][ni][0] * 0.08838834764831845f;
                    float v01 = sacc[mi][ni][1] * 0.08838834764831845f;
                    float v10 = sacc[mi][ni][2] * 0.08838834764831845f;
                    float v11 = sacc[mi][ni][3] * 0.08838834764831845f;
                    if (k0 + col     > q0 + r0) v00 = -1e30f;
                    if (k0 + col + 1 > q0 + r0) v01 = -1e30f;
                    if (k0 + col     > q0 + r1) v10 = -1e30f;
                    if (k0 + col + 1 > q0 + r1) v11 = -1e30f;
                    Ss[r0 * 68 + col] = v00; Ss[r0 * 68 + col + 1] = v01;
                    Ss[r1 * 68 + col] = v10; Ss[r1 * 68 + col + 1] = v11;
                }
            }
        }
        __syncthreads();

        // online softmax: 128 rows, 4 thr/row; P tf32-rounded; poly exp
        {
            const int rid = tid >> 2, c0 = tid & 3;
            float mx = -1e30f;
            #pragma unroll
            for (int jc = c0; jc < 64; jc += 4) mx = fmaxf(mx, Ss[rid * 68 + jc]);
            mx = fmaxf(mx, __shfl_xor_sync(0xffffffffu, mx, 1));
            mx = fmaxf(mx, __shfl_xor_sync(0xffffffffu, mx, 2));
            const float mold = mrow[rid];
            const float mnew = fmaxf(mold, mx);
            float sum = 0.f;
            #pragma unroll
            for (int jc = c0; jc < 64; jc += 4) {
                const float p = to_tf32(fexp(Ss[rid * 68 + jc] - mnew));
                Ss[rid * 68 + jc] = p;
                sum += p;
            }
            sum += __shfl_xor_sync(0xffffffffu, sum, 1);
            sum += __shfl_xor_sync(0xffffffffu, sum, 2);
            if (c0 == 0) {
                arow[rid] = fexp(mold - mnew);
                lrow[rid] = lrow[rid] * arow[rid] + sum;
                mrow[rid] = mnew;
            }
        }
        __syncthreads();

        // O^T[128d,128q] += V^T @ P^T (warp tile 32d x 32q)
        {
            const int d0 = wm << 5, qw = wn << 5;
            #pragma unroll
            for (int ni = 0; ni < 4; ni++) {
                const int cq = qw + (ni << 3) + (t4 << 1);
                const float a0 = arow[cq], a1 = arow[cq + 1];
                #pragma unroll
                for (int mi = 0; mi < 2; mi++) {
                    o[mi][ni][0] *= a0; o[mi][ni][1] *= a1;
                    o[mi][ni][2] *= a0; o[mi][ni][3] *= a1;
                }
            }
            #pragma unroll
            for (int k_ = 0; k_ < 8; k_++) {
                const int kb = k_ << 3;
                uint32_t af[2][4];
                #pragma unroll
                for (int mi = 0; mi < 2; mi++) {
                    const int dm = d0 + (mi << 4);
                    af[mi][0] = __float_as_uint(Vs[(kb + t4    ) * 132 + dm + g    ]);
                    af[mi][1] = __float_as_uint(Vs[(kb + t4    ) * 132 + dm + g + 8]);
                    af[mi][2] = __float_as_uint(Vs[(kb + t4 + 4) * 132 + dm + g    ]);
                    af[mi][3] = __float_as_uint(Vs[(kb + t4 + 4) * 132 + dm + g + 8]);
                }
                #pragma unroll
                for (int ni = 0; ni < 4; ni++) {
                    const int nq = qw + (ni << 3) + g;
                    uint32_t bf[2];
                    bf[0] = __float_as_uint(Ss[nq * 68 + kb + t4    ]);
                    bf[1] = __float_as_uint(Ss[nq * 68 + kb + t4 + 4]);
                    mma8(o[0][ni], af[0], bf);
                    mma8(o[1][ni], af[1], bf);
                }
            }
        }
    }

    // normalize + store O[q][d], d t4-major-permuted for oproj GEMM A
    __syncthreads();
    {
        const int d0 = wm << 5, qw = wn << 5;
        #pragma unroll
        for (int mi = 0; mi < 2; mi++) {
            const int pd1 = d0 + poff(g, (mi << 1));       // logical d0+mi*16+g
            const int pd2 = d0 + poff(g, (mi << 1) + 1);   // logical +8
            #pragma unroll
            for (int ni = 0; ni < 4; ni++) {
                const int cq = qw + (ni << 3) + (t4 << 1);
                const float inv0 = 1.0f / lrow[cq], inv1 = 1.0f / lrow[cq + 1];
                Og[(size_t)(q0 + cq    ) * 2048 + pd1] = to_tf32(o[mi][ni][0] * inv0);
                Og[(size_t)(q0 + cq + 1) * 2048 + pd1] = to_tf32(o[mi][ni][1] * inv1);
                Og[(size_t)(q0 + cq    ) * 2048 + pd2] = to_tf32(o[mi][ni][2] * inv0);
                Og[(size_t)(q0 + cq + 1) * 2048 + pd2] = to_tf32(o[mi][ni][3] * inv1);
            }
        }
    }
}

// ---------------- host orchestration ---------------------------------------
extern "C" void kernel_launch(void* const* d_in, const int* in_sizes, int n_in,
                              void* d_out, int out_size)
{
    const float* x     = (const float*)d_in[0];
    const float* ln1_g = (const float*)d_in[2];
    const float* ln1_b = (const float*)d_in[3];
    const float* wq    = (const float*)d_in[4];
    const float* bq    = (const float*)d_in[5];
    const float* wk    = (const float*)d_in[6];
    const float* bk    = (const float*)d_in[7];
    const float* wv    = (const float*)d_in[8];
    const float* bv    = (const float*)d_in[9];
    const float* wo    = (const float*)d_in[10];
    const float* bo    = (const float*)d_in[11];
    const float* ln2_g = (const float*)d_in[12];
    const float* ln2_b = (const float*)d_in[13];
    const float* w_in  = (const float*)d_in[14];
    const float* b_in  = (const float*)d_in[15];
    const float* w_out = (const float*)d_in[16];
    const float* b_out = (const float*)d_in[17];
    float* out = (float*)d_out;

    float *xn, *qkv, *attn, *x1, *h, *wqkvt, *wot, *wint, *woutt, *bqkv;
    cudaGetSymbolAddress((void**)&xn,     g_xn);
    cudaGetSymbolAddress((void**)&qkv,    g_qkv);
    cudaGetSymbolAddress((void**)&attn,   g_attn);
    cudaGetSymbolAddress((void**)&x1,     g_x1);
    cudaGetSymbolAddress((void**)&h,      g_h);
    cudaGetSymbolAddress((void**)&wqkvt,  g_wqkvt);
    cudaGetSymbolAddress((void**)&wot,    g_wot);
    cudaGetSymbolAddress((void**)&wint,   g_wint);
    cudaGetSymbolAddress((void**)&woutt,  g_woutt);
    cudaGetSymbolAddress((void**)&bqkv,   g_bqkv);

    cudaFuncSetAttribute(flash_kernel,
                         cudaFuncAttributeMaxDynamicSharedMemorySize, FSMEM);
    cudaFuncSetAttribute(gemm_cp<0,0,1,0>,
                         cudaFuncAttributeMaxDynamicSharedMemorySize, GSMEM);
    cudaFuncSetAttribute(gemm_cp<0,1,0,0>,
                         cudaFuncAttributeMaxDynamicSharedMemorySize, GSMEM);
    cudaFuncSetAttribute(gemm_cp<1,0,0,1>,
                         cudaFuncAttributeMaxDynamicSharedMemorySize, GSMEM);

    prep_a<<<12312, 256>>>(wq, wk, wv, bq, bk, bv);                     // 1
    prep_b<<<36864, 256>>>(wo, w_in, w_out);                            // 2
    ln_kernel<<<4096, 256>>>(x, ln1_g, ln1_b, xn);                      // 3
    gemm_cp<0,0,1,0><<<dim3(48, 32), 256, GSMEM>>>(                     // 4: QKV
        xn, wqkvt, bqkv, nullptr, qkv, 4096, 6144, 2048);
    flash_kernel<<<dim3(16, 32), 512, FSMEM>>>(qkv, attn);              // 5
    gemm_cp<0,1,0,0><<<dim3(16, 32), 256, GSMEM>>>(                     // 6: O-proj
        attn, wot, bo, x, x1, 4096, 2048, 2048);
    ln_kernel<<<4096, 256>>>(x1, ln2_g, ln2_b, xn);                     // 7
    gemm_cp<1,0,0,1><<<dim3(64, 32), 256, GSMEM>>>(                     // 8: MLP in
        xn, wint, b_in, nullptr, h, 4096, 8192, 2048);
    gemm_cp<0,1,0,0><<<dim3(16, 32), 256, GSMEM>>>(                     // 9: MLP out
        h, woutt, b_out, x1, out, 4096, 2048, 8192);
}

// round 16
// speedup vs baseline: 1.1893x; 1.1893x over previous
#include <cuda_runtime.h>
#include <cstdint>
#include <math.h>

#define BSD 8388608
#define BSF 33554432

__device__ float g_xn[BSD];
__device__ float g_qkv[25165824];
__device__ float g_attn[BSD];
__device__ float g_x1[BSD];
__device__ float g_h[BSF];
__device__ float g_wqkvt[12582912];
__device__ float g_wot[4194304];
__device__ float g_wint[16777216];
__device__ float g_woutt[16777216];
__device__ float g_bqkv[6144];

__device__ __forceinline__ float to_tf32(float x) {
    float r; asm("cvt.rna.tf32.f32 %0, %1;" : "=f"(r) : "f"(x)); return r;
}
__device__ __forceinline__ uint32_t smem_u32(const void* p) {
    uint32_t a;
    asm("{ .reg .u64 t; cvta.to.shared.u64 t, %1; cvt.u32.u64 %0, t; }"
        : "=r"(a) : "l"(p));
    return a;
}
__device__ __forceinline__ void cp16(uint32_t s, const void* g) {
    asm volatile("cp.async.cg.shared.global [%0], [%1], 16;" :: "r"(s), "l"(g));
}
__device__ __forceinline__ void mma8(float* d, const uint32_t* a, const uint32_t* b) {
    asm volatile(
        "mma.sync.aligned.m16n8k8.row.col.f32.tf32.tf32.f32 "
        "{%0,%1,%2,%3}, {%4,%5,%6,%7}, {%8,%9}, {%0,%1,%2,%3};\n"
        : "+f"(d[0]), "+f"(d[1]), "+f"(d[2]), "+f"(d[3])
        : "r"(a[0]), "r"(a[1]), "r"(a[2]), "r"(a[3]), "r"(b[0]), "r"(b[1]));
}
__device__ __forceinline__ float gelu_f(float v) {
    return 0.5f * v * (1.0f + erff(v * 0.70710678118654752f));
}
__device__ __forceinline__ float fexp(float x) {
    float y = x * 1.4426950408889634f;
    y = fmaxf(y, -126.0f);
    const float magic = 12582912.0f;
    const float z = y + magic;
    const int   n = __float_as_int(z) - 0x4B400000;
    const float f = y - (z - magic);
    float r = 0.0013333558f;
    r = fmaf(r, f, 0.0096181291f);
    r = fmaf(r, f, 0.0555041087f);
    r = fmaf(r, f, 0.2402265069f);
    r = fmaf(r, f, 0.6931471806f);
    r = fmaf(r, f, 1.0f);
    return __int_as_float(__float_as_int(r) + (n << 23));
}
// pair-permutation within 8-groups: logical l -> phys (l<4 ? 2l : 2(l-4)+1)
__device__ __forceinline__ int permc(int x) {
    const int l = x & 7;
    return (x & 24) | ((l < 4) ? (l << 1) : (((l - 4) << 1) | 1));
}

// ---------------- weight prep ----------------------------------------------
__device__ void tp_tile(const float* __restrict__ src, float* __restrict__ dst,
                        int K, int N, int t)
{
    __shared__ float tbuf[32][33];
    const int tn = N >> 5;
    const int n0 = (t % tn) << 5, k0 = (t / tn) << 5;
    const int x = threadIdx.x & 31, y = threadIdx.x >> 5;
    #pragma unroll
    for (int i = 0; i < 32; i += 8)
        tbuf[y + i][x] = src[(size_t)(k0 + y + i) * N + n0 + x];
    __syncthreads();
    const int kp = k0 + permc(x);
    #pragma unroll
    for (int i = 0; i < 32; i += 8)
        dst[(size_t)(n0 + y + i) * K + kp] = to_tf32(tbuf[x][y + i]);
}

__global__ __launch_bounds__(256) void prep_a(
    const float* __restrict__ wq, const float* __restrict__ wk,
    const float* __restrict__ wv, const float* __restrict__ bq,
    const float* __restrict__ bk, const float* __restrict__ bv)
{
    const int blk = blockIdx.x;
    if (blk < 12288) {
        const int w = blk >> 12, t = blk & 4095;
        const float* src = (w == 0) ? wq : (w == 1) ? wk : wv;
        tp_tile(src, g_wqkvt + (size_t)w * 4194304, 2048, 2048, t);
    } else {
        const int idx = ((blk - 12288) << 8) + threadIdx.x;
        if (idx < 6144) {
            const int sel = idx >> 11;
            const float* b = (sel == 0) ? bq : (sel == 1) ? bk : bv;
            g_bqkv[idx] = b[idx & 2047];
        }
    }
}

__global__ __launch_bounds__(256) void prep_b(
    const float* __restrict__ wo, const float* __restrict__ w_in,
    const float* __restrict__ w_out)
{
    const int blk = blockIdx.x;
    if (blk < 4096)        tp_tile(wo,    g_wot,   2048, 2048, blk);
    else if (blk < 20480)  tp_tile(w_in,  g_wint,  2048, 8192, blk - 4096);
    else                   tp_tile(w_out, g_woutt, 8192, 2048, blk - 20480);
}

// ---------------- block reduce + LayerNorm ---------------------------------
__device__ __forceinline__ float block_sum256(float v) {
    __shared__ float red[8];
    #pragma unroll
    for (int o = 16; o; o >>= 1) v += __shfl_xor_sync(0xffffffffu, v, o);
    const int w = threadIdx.x >> 5, l = threadIdx.x & 31;
    __syncthreads();
    if (l == 0) red[w] = v;
    __syncthreads();
    float t = red[l & 7];
    t += __shfl_xor_sync(0xffffffffu, t, 1);
    t += __shfl_xor_sync(0xffffffffu, t, 2);
    t += __shfl_xor_sync(0xffffffffu, t, 4);
    return t;
}

__global__ __launch_bounds__(256) void ln_kernel(
    const float* __restrict__ x, const float* __restrict__ gw,
    const float* __restrict__ bw, float* __restrict__ y)
{
    const size_t base = (size_t)blockIdx.x * 2048;
    const int c0 = threadIdx.x << 3;
    const float4 v0 = *(const float4*)&x[base + c0];
    const float4 v1 = *(const float4*)&x[base + c0 + 4];

    float s = v0.x + v0.y + v0.z + v0.w + v1.x + v1.y + v1.z + v1.w;
    const float mean = block_sum256(s) * (1.0f / 2048.0f);

    float d[8];
    d[0] = v0.x - mean; d[1] = v0.y - mean; d[2] = v0.z - mean; d[3] = v0.w - mean;
    d[4] = v1.x - mean; d[5] = v1.y - mean; d[6] = v1.z - mean; d[7] = v1.w - mean;
    float q = 0.f;
    #pragma unroll
    for (int i = 0; i < 8; i++) q += d[i] * d[i];
    const float var = block_sum256(q) * (1.0f / 2048.0f);
    const float rs = rsqrtf(var + 1e-5f);

    const float4 g0 = *(const float4*)&gw[c0];
    const float4 g1 = *(const float4*)&gw[c0 + 4];
    const float4 b0 = *(const float4*)&bw[c0];
    const float4 b1 = *(const float4*)&bw[c0 + 4];
    const float ga[8] = {g0.x, g0.y, g0.z, g0.w, g1.x, g1.y, g1.z, g1.w};
    const float ba[8] = {b0.x, b0.y, b0.z, b0.w, b1.x, b1.y, b1.z, b1.w};

    float o[8];
    #pragma unroll
    for (int i = 0; i < 8; i++) o[i] = to_tf32(d[i] * rs * ga[i] + ba[i]);

    #pragma unroll
    for (int i = 0; i < 4; i++)
        *(float2*)&y[base + c0 + (i << 1)] = make_float2(o[i], o[i + 4]);
}

// ---------------- TF32 GEMM (exact R11 570us version) ----------------------
#define GSMEM 98304

template<int ACT, int HASRES, int RND, int PERMC>
__global__ __launch_bounds__(256, 2) void gemm_cp(
    const float* __restrict__ A, const float* __restrict__ Wt,
    const float* __restrict__ bias, const float* __restrict__ res,
    float* __restrict__ C, int M, int N, int K)
{
    extern __shared__ float sm[];
    const uint32_t sb = smem_u32(sm);
    const int tid = threadIdx.x;
    const int warp = tid >> 5, lane = tid & 31;
    const int wm = warp >> 1, wn = warp & 1;
    const int g = lane >> 2, t4 = lane & 3;
    const int bm = blockIdx.y << 7, bn = blockIdx.x << 7;

    const float* Ab = A  + (size_t)bm * K;
    const float* Bb = Wt + (size_t)bn * K;
    const int KT = K >> 5;

    const int r0 = tid >> 3;
    const int cc = (tid & 7) << 2;
    const uint32_t dcol = (uint32_t)((cc ^ ((r0 & 3) << 3)) << 2);
    const float* ga[4]; const float* gb[4];
    uint32_t da[4], db[4];
    #pragma unroll
    for (int i = 0; i < 4; i++) {
        const int row = r0 + (i << 5);
        ga[i] = Ab + (size_t)row * K + cc;
        gb[i] = Bb + (size_t)row * K + cc;
        da[i] = (uint32_t)(row * 128) + dcol;
        db[i] = 16384u + (uint32_t)(row * 128) + dcol;
    }

    float acc[2][8][4];
    #pragma unroll
    for (int a = 0; a < 2; a++)
        #pragma unroll
        for (int b2 = 0; b2 < 8; b2++)
            #pragma unroll
            for (int c = 0; c < 4; c++) acc[a][b2][c] = 0.f;

    auto issue = [&](int s) {
        const uint32_t st = sb + (uint32_t)s * 32768u;
        #pragma unroll
        for (int i = 0; i < 4; i++) { cp16(st + da[i], ga[i]); ga[i] += 32; }
        #pragma unroll
        for (int i = 0; i < 4; i++) { cp16(st + db[i], gb[i]); gb[i] += 32; }
        asm volatile("cp.async.commit_group;" ::: "memory");
    };

    issue(0);
    issue(1);

    const int swz = (g & 3) << 3;
    int kcs[4];
    #pragma unroll
    for (int ks = 0; ks < 4; ks++) kcs[ks] = ((ks << 3) ^ swz) | (t4 << 1);

    int s = 0;
    for (int kt = 0; kt < KT; kt++) {
        if (kt + 1 < KT) asm volatile("cp.async.wait_group 1;" ::: "memory");
        else             asm volatile("cp.async.wait_group 0;" ::: "memory");
        __syncthreads();
        if (kt + 2 < KT) {
            int ns = s + 2; if (ns >= 3) ns -= 3;
            issue(ns);
        }
        const float* As = sm + s * 8192;
        const float* Bs = As + 4096;

        #pragma unroll
        for (int ks = 0; ks < 4; ks++) {
            const int kc = kcs[ks];
            uint32_t af[2][4];
            #pragma unroll
            for (int mi = 0; mi < 2; mi++) {
                const int mr = (wm << 5) + (mi << 4) + g;
                const float2 a02 = *(const float2*)&As[mr * 32 + kc];
                const float2 a13 = *(const float2*)&As[(mr + 8) * 32 + kc];
                af[mi][0] = __float_as_uint(a02.x);
                af[mi][1] = __float_as_uint(a13.x);
                af[mi][2] = __float_as_uint(a02.y);
                af[mi][3] = __float_as_uint(a13.y);
            }
            #pragma unroll
            for (int ni = 0; ni < 8; ni++) {
                const int nc = (wn << 6) + (ni << 3) + g;
                const float2 b01 = *(const float2*)&Bs[nc * 32 + kc];
                uint32_t bf[2];
                bf[0] = __float_as_uint(b01.x);
                bf[1] = __float_as_uint(b01.y);
                mma8(acc[0][ni], af[0], bf);
                mma8(acc[1][ni], af[1], bf);
            }
        }
        if (++s == 3) s = 0;
    }

    #pragma unroll
    for (int mi = 0; mi < 2; mi++) {
        const int row0 = bm + (wm << 5) + (mi << 4) + g;
        #pragma unroll
        for (int ni = 0; ni < 8; ni++) {
            const int base = bn + (wn << 6) + (ni << 3);
            const int lcol = base + (t4 << 1);
            const float b0 = bias[lcol], b1 = bias[lcol + 1];
            float v00 = acc[mi][ni][0] + b0, v01 = acc[mi][ni][1] + b1;
            float v10 = acc[mi][ni][2] + b0, v11 = acc[mi][ni][3] + b1;
            const size_t i0 = (size_t)row0 * N + lcol;
            const size_t i1 = i0 + (size_t)8 * N;
            if (HASRES) {
                v00 += res[i0]; v01 += res[i0 + 1];
                v10 += res[i1]; v11 += res[i1 + 1];
            }
            if (ACT == 1) {
                v00 = to_tf32(gelu_f(v00)); v01 = to_tf32(gelu_f(v01));
                v10 = to_tf32(gelu_f(v10)); v11 = to_tf32(gelu_f(v11));
            } else if (RND) {
                v00 = to_tf32(v00); v01 = to_tf32(v01);
                v10 = to_tf32(v10); v11 = to_tf32(v11);
            }
            if (PERMC) {
                const int p0 = (t4 < 2) ? (t4 << 2) : ((t4 << 2) - 7);
                const size_t r0i = (size_t)row0 * N + base;
                const size_t r1i = r0i + (size_t)8 * N;
                C[r0i + p0] = v00; C[r0i + p0 + 2] = v01;
                C[r1i + p0] = v10; C[r1i + p0 + 2] = v11;
            } else {
                *(float2*)&C[i0] = make_float2(v00, v01);
                *(float2*)&C[i1] = make_float2(v10, v11);
            }
        }
    }
}

// ---------------- causal flash attention: pair-permuted frags --------------
// QKV buffer is PERMC-permuted (all 6144 cols). QK frags load float2;
// Ss stored pair-permuted -> PV B-frags float2; O stored in permc space.
// smem floats: Qs[128][136]=17408 | Ks[64][136]=8704 | Vs[64][136]=8704 |
//              Ss[128][72]=9216 | m/l/a[128]x3 ; total 44416 f = 177664 B
#define FSMEM 177664

__global__ __launch_bounds__(512, 1) void flash_kernel(
    const float* __restrict__ QKV, float* __restrict__ O)
{
    extern __shared__ float smf[];
    float* Qs   = smf;                 // [128][136]
    float* Ks   = smf + 17408;         // [64][136]
    float* Vs   = smf + 26112;         // [64][136]
    float* Ss   = smf + 34816;         // [128][72]
    float* mrow = smf + 44032;
    float* lrow = smf + 44160;
    float* arow = smf + 44288;

    const int tid = threadIdx.x;
    const int warp = tid >> 5, lane = tid & 31;
    const int g = lane >> 2, t4 = lane & 3;
    const int wm = warp >> 2, wn = warp & 3;
    const int b = blockIdx.y >> 4, h = blockIdx.y & 15;
    const int qi = (int)gridDim.x - 1 - (int)blockIdx.x;   // heaviest first
    const int q0 = qi << 7;
    const size_t qbase = (size_t)b * 2048 * 6144 + (size_t)h * 128;
    const float* Qg = QKV + qbase;
    const float* Kg = QKV + qbase + 2048;
    const float* Vg = QKV + qbase + 4096;
    float*       Og = O + ((size_t)b * 2048) * 2048 + (size_t)h * 128;

    #pragma unroll
    for (int rr = 0; rr < 8; rr++) {
        const int f4 = tid + (rr << 9);
        const int row = f4 >> 5, c4 = f4 & 31;
        *(float4*)&Qs[row * 136 + (c4 << 2)] =
            *(const float4*)&Qg[(size_t)(q0 + row) * 6144 + (c4 << 2)];
    }
    if (tid < 128) { mrow[tid] = -1e30f; lrow[tid] = 0.f; }

    float o[2][4][4];
    #pragma unroll
    for (int mi = 0; mi < 2; mi++)
        #pragma unroll
        for (int ni = 0; ni < 4; ni++)
            #pragma unroll
            for (int c = 0; c < 4; c++) o[mi][ni][c] = 0.f;

    const int ntile = (qi << 1) + 2;
    for (int kt = 0; kt < ntile; kt++) {
        const int k0 = kt << 6;
        __syncthreads();
        #pragma unroll
        for (int rr = 0; rr < 4; rr++) {
            const int f4 = tid + (rr << 9);
            const int row = f4 >> 5, c4 = f4 & 31;
            *(float4*)&Ks[row * 136 + (c4 << 2)] =
                *(const float4*)&Kg[(size_t)(k0 + row) * 6144 + (c4 << 2)];
            *(float4*)&Vs[row * 136 + (c4 << 2)] =
                *(const float4*)&Vg[(size_t)(k0 + row) * 6144 + (c4 << 2)];
        }
        __syncthreads();

        // S[128,64] = Q K^T (warp tile 32q x 16n); float2 frags (d-paired)
        {
            float sacc[2][2][4];
            #pragma unroll
            for (int mi = 0; mi < 2; mi++)
                #pragma unroll
                for (int ni = 0; ni < 2; ni++)
                    #pragma unroll
                    for (int c = 0; c < 4; c++) sacc[mi][ni][c] = 0.f;
            const int m0 = wm << 5, nb = wn << 4;
            #pragma unroll
            for (int kk = 0; kk < 16; kk++) {
                const int kb2 = (kk << 3) + (t4 << 1);
                uint32_t af[2][4];
                #pragma unroll
                for (int mi = 0; mi < 2; mi++) {
                    const int mr = m0 + (mi << 4) + g;
                    const float2 a02 = *(const float2*)&Qs[mr * 136 + kb2];
                    const float2 a13 = *(const float2*)&Qs[(mr + 8) * 136 + kb2];
                    af[mi][0] = __float_as_uint(a02.x);
                    af[mi][1] = __float_as_uint(a13.x);
                    af[mi][2] = __float_as_uint(a02.y);
                    af[mi][3] = __float_as_uint(a13.y);
                }
                #pragma unroll
                for (int ni = 0; ni < 2; ni++) {
                    const int n = nb + (ni << 3) + g;
                    const float2 bv = *(const float2*)&Ks[n * 136 + kb2];
                    uint32_t bf[2];
                    bf[0] = __float_as_uint(bv.x);
                    bf[1] = __float_as_uint(bv.y);
                    mma8(sacc[0][ni], af[0], bf);
                    mma8(sacc[1][ni], af[1], bf);
                }
            }
            // store S pair-permuted: logical (2t4,2t4+1) -> phys (p0, p0+2)
            const int p0 = (t4 < 2) ? (t4 << 2) : ((t4 << 2) - 7);
            #pragma unroll
            for (int mi = 0; mi < 2; mi++) {
                const int r0 = m0 + (mi << 4) + g, r1 = r0 + 8;
                #pragma unroll
                for (int ni = 0; ni < 2; ni++) {
                    const int cb = nb + (ni << 3);
                    const int col = cb + (t4 << 1);
                    float v00 = sacc[mi][ni][0] * 0.08838834764831845f;
                    float v01 = sacc[mi][ni][1] * 0.08838834764831845f;
                    float v10 = sacc[mi][ni][2] * 0.08838834764831845f;
                    float v11 = sacc[mi][ni][3] * 0.08838834764831845f;
                    if (k0 + col     > q0 + r0) v00 = -1e30f;
                    if (k0 + col + 1 > q0 + r0) v01 = -1e30f;
                    if (k0 + col     > q0 + r1) v10 = -1e30f;
                    if (k0 + col + 1 > q0 + r1) v11 = -1e30f;
                    Ss[r0 * 72 + cb + p0] = v00; Ss[r0 * 72 + cb + p0 + 2] = v01;
                    Ss[r1 * 72 + cb + p0] = v10; Ss[r1 * 72 + cb + p0 + 2] = v11;
                }
            }
        }
        __syncthreads();

        // online softmax: 128 rows, 4 thr/row (permutation-invariant)
        {
            const int rid = tid >> 2, c0 = tid & 3;
            float mx = -1e30f;
            #pragma unroll
            for (int jc = c0; jc < 64; jc += 4) mx = fmaxf(mx, Ss[rid * 72 + jc]);
            mx = fmaxf(mx, __shfl_xor_sync(0xffffffffu, mx, 1));
            mx = fmaxf(mx, __shfl_xor_sync(0xffffffffu, mx, 2));
            const float mold = mrow[rid];
            const float mnew = fmaxf(mold, mx);
            float sum = 0.f;
            #pragma unroll
            for (int jc = c0; jc < 64; jc += 4) {
                const float p = to_tf32(fexp(Ss[rid * 72 + jc] - mnew));
                Ss[rid * 72 + jc] = p;
                sum += p;
            }
            sum += __shfl_xor_sync(0xffffffffu, sum, 1);
            sum += __shfl_xor_sync(0xffffffffu, sum, 2);
            if (c0 == 0) {
                arow[rid] = fexp(mold - mnew);
                lrow[rid] = lrow[rid] * arow[rid] + sum;
                mrow[rid] = mnew;
            }
        }
        __syncthreads();

        // O^T += V^T @ P^T (warp 32d x 32q); B-frags float2 (seq-paired)
        {
            const int d0 = wm << 5, qw = wn << 5;
            #pragma unroll
            for (int ni = 0; ni < 4; ni++) {
                const int cq = qw + (ni << 3) + (t4 << 1);
                const float a0 = arow[cq], a1 = arow[cq + 1];
                #pragma unroll
                for (int mi = 0; mi < 2; mi++) {
                    o[mi][ni][0] *= a0; o[mi][ni][1] *= a1;
                    o[mi][ni][2] *= a0; o[mi][ni][3] *= a1;
                }
            }
            #pragma unroll
            for (int k_ = 0; k_ < 8; k_++) {
                const int kb = k_ << 3;
                uint32_t af[2][4];
                #pragma unroll
                for (int mi = 0; mi < 2; mi++) {
                    const int dm = d0 + (mi << 4);
                    af[mi][0] = __float_as_uint(Vs[(kb + t4    ) * 136 + dm + g    ]);
                    af[mi][1] = __float_as_uint(Vs[(kb + t4    ) * 136 + dm + g + 8]);
                    af[mi][2] = __float_as_uint(Vs[(kb + t4 + 4) * 136 + dm + g    ]);
                    af[mi][3] = __float_as_uint(Vs[(kb + t4 + 4) * 136 + dm + g + 8]);
                }
                #pragma unroll
                for (int ni = 0; ni < 4; ni++) {
                    const int nq = qw + (ni << 3) + g;
                    const float2 bv = *(const float2*)&Ss[nq * 72 + kb + (t4 << 1)];
                    uint32_t bf[2];
                    bf[0] = __float_as_uint(bv.x);
                    bf[1] = __float_as_uint(bv.y);
                    mma8(o[0][ni], af[0], bf);
                    mma8(o[1][ni], af[1], bf);
                }
            }
        }
    }

    // normalize + store O[q][d] directly (already in permc space via V)
    __syncthreads();
    {
        const int d0 = wm << 5, qw = wn << 5;
        #pragma unroll
        for (int ni = 0; ni < 4; ni++) {
            const int cq = qw + (ni << 3) + (t4 << 1);
            const float inv0 = 1.0f / lrow[cq], inv1 = 1.0f / lrow[cq + 1];
            #pragma unroll
            for (int mi = 0; mi < 2; mi++) {
                const int db = d0 + (mi << 4);
                Og[(size_t)(q0 + cq    ) * 2048 + db + g    ] = to_tf32(o[mi][ni][0] * inv0);
                Og[(size_t)(q0 + cq + 1) * 2048 + db + g    ] = to_tf32(o[mi][ni][1] * inv1);
                Og[(size_t)(q0 + cq    ) * 2048 + db + g + 8] = to_tf32(o[mi][ni][2] * inv0);
                Og[(size_t)(q0 + cq + 1) * 2048 + db + g + 8] = to_tf32(o[mi][ni][3] * inv1);
            }
        }
    }
}

// ---------------- host orchestration ---------------------------------------
extern "C" void kernel_launch(void* const* d_in, const int* in_sizes, int n_in,
                              void* d_out, int out_size)
{
    const float* x     = (const float*)d_in[0];
    const float* ln1_g = (const float*)d_in[2];
    const float* ln1_b = (const float*)d_in[3];
    const float* wq    = (const float*)d_in[4];
    const float* bq    = (const float*)d_in[5];
    const float* wk    = (const float*)d_in[6];
    const float* bk    = (const float*)d_in[7];
    const float* wv    = (const float*)d_in[8];
    const float* bv    = (const float*)d_in[9];
    const float* wo    = (const float*)d_in[10];
    const float* bo    = (const float*)d_in[11];
    const float* ln2_g = (const float*)d_in[12];
    const float* ln2_b = (const float*)d_in[13];
    const float* w_in  = (const float*)d_in[14];
    const float* b_in  = (const float*)d_in[15];
    const float* w_out = (const float*)d_in[16];
    const float* b_out = (const float*)d_in[17];
    float* out = (float*)d_out;

    float *xn, *qkv, *attn, *x1, *h, *wqkvt, *wot, *wint, *woutt, *bqkv;
    cudaGetSymbolAddress((void**)&xn,     g_xn);
    cudaGetSymbolAddress((void**)&qkv,    g_qkv);
    cudaGetSymbolAddress((void**)&attn,   g_attn);
    cudaGetSymbolAddress((void**)&x1,     g_x1);
    cudaGetSymbolAddress((void**)&h,      g_h);
    cudaGetSymbolAddress((void**)&wqkvt,  g_wqkvt);
    cudaGetSymbolAddress((void**)&wot,    g_wot);
    cudaGetSymbolAddress((void**)&wint,   g_wint);
    cudaGetSymbolAddress((void**)&woutt,  g_woutt);
    cudaGetSymbolAddress((void**)&bqkv,   g_bqkv);

    cudaFuncSetAttribute(flash_kernel,
                         cudaFuncAttributeMaxDynamicSharedMemorySize, FSMEM);
    cudaFuncSetAttribute(gemm_cp<0,0,1,1>,
                         cudaFuncAttributeMaxDynamicSharedMemorySize, GSMEM);
    cudaFuncSetAttribute(gemm_cp<0,1,0,0>,
                         cudaFuncAttributeMaxDynamicSharedMemorySize, GSMEM);
    cudaFuncSetAttribute(gemm_cp<1,0,0,1>,
                         cudaFuncAttributeMaxDynamicSharedMemorySize, GSMEM);

    prep_a<<<12312, 256>>>(wq, wk, wv, bq, bk, bv);                     // 1
    prep_b<<<36864, 256>>>(wo, w_in, w_out);                            // 2
    ln_kernel<<<4096, 256>>>(x, ln1_g, ln1_b, xn);                      // 3
    gemm_cp<0,0,1,1><<<dim3(48, 32), 256, GSMEM>>>(                     // 4: QKV (permuted out)
        xn, wqkvt, g_bqkv, nullptr, qkv, 4096, 6144, 2048);
    flash_kernel<<<dim3(16, 32), 512, FSMEM>>>(qkv, attn);              // 5
    gemm_cp<0,1,0,0><<<dim3(16, 32), 256, GSMEM>>>(                     // 6: O-proj
        attn, wot, bo, x, x1, 4096, 2048, 2048);
    ln_kernel<<<4096, 256>>>(x1, ln2_g, ln2_b, xn);                     // 7
    gemm_cp<1,0,0,1><<<dim3(64, 32), 256, GSMEM>>>(                     // 8: MLP in
        xn, wint, b_in, nullptr, h, 4096, 8192, 2048);
    gemm_cp<0,1,0,0><<<dim3(16, 32), 256, GSMEM>>>(                     // 9: MLP out
        h, woutt, b_out, x1, out, 4096, 2048, 8192);
}

// round 17
// speedup vs baseline: 2.1060x; 1.7709x over previous
#include <cuda_runtime.h>
#include <cuda_fp16.h>
#include <cstdint>
#include <math.h>

#define BSD 8388608
#define BSF 33554432

// fp32 buffers
__device__ float g_x1[BSD];
__device__ float g_bqkv[6144];
// fp16 buffers
__device__ __half g_xn[BSD];
__device__ __half g_qkv[25165824];   // [4096][6144]
__device__ __half g_attn[BSD];
__device__ __half g_h[BSF];
__device__ __half g_wqkvt[12582912]; // [6144][2048]
__device__ __half g_wot[4194304];
__device__ __half g_wint[16777216];
__device__ __half g_woutt[16777216];

__device__ __forceinline__ uint32_t smem_u32(const void* p) {
    uint32_t a;
    asm("{ .reg .u64 t; cvta.to.shared.u64 t, %1; cvt.u32.u64 %0, t; }"
        : "=r"(a) : "l"(p));
    return a;
}
__device__ __forceinline__ void cp16(uint32_t s, const void* g) {
    asm volatile("cp.async.cg.shared.global [%0], [%1], 16;" :: "r"(s), "l"(g));
}
__device__ __forceinline__ void mma16(float* d, const uint32_t* a, const uint32_t* b) {
    asm volatile(
        "mma.sync.aligned.m16n8k16.row.col.f32.f16.f16.f32 "
        "{%0,%1,%2,%3}, {%4,%5,%6,%7}, {%8,%9}, {%0,%1,%2,%3};\n"
        : "+f"(d[0]), "+f"(d[1]), "+f"(d[2]), "+f"(d[3])
        : "r"(a[0]), "r"(a[1]), "r"(a[2]), "r"(a[3]), "r"(b[0]), "r"(b[1]));
}
__device__ __forceinline__ float gelu_f(float v) {
    return 0.5f * v * (1.0f + erff(v * 0.70710678118654752f));
}
__device__ __forceinline__ float fexp(float x) {
    float y = x * 1.4426950408889634f;
    y = fmaxf(y, -126.0f);
    const float magic = 12582912.0f;
    const float z = y + magic;
    const int   n = __float_as_int(z) - 0x4B400000;
    const float f = y - (z - magic);
    float r = 0.0013333558f;
    r = fmaf(r, f, 0.0096181291f);
    r = fmaf(r, f, 0.0555041087f);
    r = fmaf(r, f, 0.2402265069f);
    r = fmaf(r, f, 0.6931471806f);
    r = fmaf(r, f, 1.0f);
    return __int_as_float(__float_as_int(r) + (n << 23));
}

// ---------------- weight prep: transpose [K,N]->[N,K], round to half -------
__device__ void tp_tile(const float* __restrict__ src, __half* __restrict__ dst,
                        int K, int N, int t)
{
    __shared__ float tbuf[32][33];
    const int tn = N >> 5;
    const int n0 = (t % tn) << 5, k0 = (t / tn) << 5;
    const int x = threadIdx.x & 31, y = threadIdx.x >> 5;
    #pragma unroll
    for (int i = 0; i < 32; i += 8)
        tbuf[y + i][x] = src[(size_t)(k0 + y + i) * N + n0 + x];
    __syncthreads();
    #pragma unroll
    for (int i = 0; i < 32; i += 8)
        dst[(size_t)(n0 + y + i) * K + k0 + x] = __float2half_rn(tbuf[x][y + i]);
}

__global__ __launch_bounds__(256) void prep_a(
    const float* __restrict__ wq, const float* __restrict__ wk,
    const float* __restrict__ wv, const float* __restrict__ bq,
    const float* __restrict__ bk, const float* __restrict__ bv)
{
    const int blk = blockIdx.x;
    if (blk < 12288) {
        const int w = blk >> 12, t = blk & 4095;
        const float* src = (w == 0) ? wq : (w == 1) ? wk : wv;
        tp_tile(src, g_wqkvt + (size_t)w * 4194304, 2048, 2048, t);
    } else {
        const int idx = ((blk - 12288) << 8) + threadIdx.x;
        if (idx < 6144) {
            const int sel = idx >> 11;
            const float* b = (sel == 0) ? bq : (sel == 1) ? bk : bv;
            g_bqkv[idx] = b[idx & 2047];
        }
    }
}

__global__ __launch_bounds__(256) void prep_b(
    const float* __restrict__ wo, const float* __restrict__ w_in,
    const float* __restrict__ w_out)
{
    const int blk = blockIdx.x;
    if (blk < 4096)        tp_tile(wo,    g_wot,   2048, 2048, blk);
    else if (blk < 20480)  tp_tile(w_in,  g_wint,  2048, 8192, blk - 4096);
    else                   tp_tile(w_out, g_woutt, 8192, 2048, blk - 20480);
}

// ---------------- block reduce + LayerNorm (half out) ----------------------
__device__ __forceinline__ float block_sum256(float v) {
    __shared__ float red[8];
    #pragma unroll
    for (int o = 16; o; o >>= 1) v += __shfl_xor_sync(0xffffffffu, v, o);
    const int w = threadIdx.x >> 5, l = threadIdx.x & 31;
    __syncthreads();
    if (l == 0) red[w] = v;
    __syncthreads();
    float t = red[l & 7];
    t += __shfl_xor_sync(0xffffffffu, t, 1);
    t += __shfl_xor_sync(0xffffffffu, t, 2);
    t += __shfl_xor_sync(0xffffffffu, t, 4);
    return t;
}

__global__ __launch_bounds__(256) void ln_kernel(
    const float* __restrict__ x, const float* __restrict__ gw,
    const float* __restrict__ bw, __half* __restrict__ y)
{
    const size_t base = (size_t)blockIdx.x * 2048;
    const int c0 = threadIdx.x << 3;
    const float4 v0 = *(const float4*)&x[base + c0];
    const float4 v1 = *(const float4*)&x[base + c0 + 4];

    float s = v0.x + v0.y + v0.z + v0.w + v1.x + v1.y + v1.z + v1.w;
    const float mean = block_sum256(s) * (1.0f / 2048.0f);

    float d[8];
    d[0] = v0.x - mean; d[1] = v0.y - mean; d[2] = v0.z - mean; d[3] = v0.w - mean;
    d[4] = v1.x - mean; d[5] = v1.y - mean; d[6] = v1.z - mean; d[7] = v1.w - mean;
    float q = 0.f;
    #pragma unroll
    for (int i = 0; i < 8; i++) q += d[i] * d[i];
    const float var = block_sum256(q) * (1.0f / 2048.0f);
    const float rs = rsqrtf(var + 1e-5f);

    const float4 g0 = *(const float4*)&gw[c0];
    const float4 g1 = *(const float4*)&gw[c0 + 4];
    const float4 b0 = *(const float4*)&bw[c0];
    const float4 b1 = *(const float4*)&bw[c0 + 4];
    const float ga[8] = {g0.x, g0.y, g0.z, g0.w, g1.x, g1.y, g1.z, g1.w};
    const float ba[8] = {b0.x, b0.y, b0.z, b0.w, b1.x, b1.y, b1.z, b1.w};

    #pragma unroll
    for (int j = 0; j < 4; j++) {
        const __half2 hv = __halves2half2(
            __float2half_rn(d[2*j]     * rs * ga[2*j]     + ba[2*j]),
            __float2half_rn(d[2*j + 1] * rs * ga[2*j + 1] + ba[2*j + 1]));
        *(__half2*)&y[base + c0 + 2*j] = hv;
    }
}

// ---------------- FP16 GEMM: K-tile 64, XOR-8 swizzle, 3 stages ------------
// C[M,N] = A[M,K] @ Wt[N,K]^T (+bias)(+res)(+gelu). A,Wt half; acc fp32.
// Stage: A 128x128B + B 128x128B = 32KB; 3 stages = 96KB.
#define GSMEM 98304

template<int ACT, int HASRES, int OUTH>
__global__ __launch_bounds__(256, 2) void gemm_cp(
    const __half* __restrict__ A, const __half* __restrict__ Wt,
    const float* __restrict__ bias, const float* __restrict__ res,
    float* __restrict__ Cf, __half* __restrict__ Ch, int M, int N, int K)
{
    extern __shared__ char smc[];
    const uint32_t sb = smem_u32(smc);
    const int tid = threadIdx.x;
    const int warp = tid >> 5, lane = tid & 31;
    const int wm = warp >> 1, wn = warp & 1;
    const int g = lane >> 2, t4 = lane & 3;
    const int bm = blockIdx.y << 7, bn = blockIdx.x << 7;

    const int KT = K >> 6;

    // copy geometry: 8 chunks of 16B per 128B row; XOR-8 swizzle
    const int r0 = tid >> 3, ch = tid & 7;
    const uint32_t dst0 = (uint32_t)(r0 * 128 + ((ch ^ (r0 & 7)) << 4));
    const __half* ga[4]; const __half* gb[4];
    uint32_t da[4], db[4];
    #pragma unroll
    for (int i = 0; i < 4; i++) {
        const int row = r0 + (i << 5);
        ga[i] = A  + (size_t)(bm + row) * K + ch * 8;
        gb[i] = Wt + (size_t)(bn + row) * K + ch * 8;
        da[i] = (uint32_t)(row * 128 + ((ch ^ (row & 7)) << 4));
        db[i] = 16384u + da[i];
    }

    float acc[2][8][4];
    #pragma unroll
    for (int a = 0; a < 2; a++)
        #pragma unroll
        for (int b2 = 0; b2 < 8; b2++)
            #pragma unroll
            for (int c = 0; c < 4; c++) acc[a][b2][c] = 0.f;

    auto issue = [&](int s) {
        const uint32_t st = sb + (uint32_t)s * 32768u;
        #pragma unroll
        for (int i = 0; i < 4; i++) { cp16(st + da[i], ga[i]); ga[i] += 64; }
        #pragma unroll
        for (int i = 0; i < 4; i++) { cp16(st + db[i], gb[i]); gb[i] += 64; }
        asm volatile("cp.async.commit_group;" ::: "memory");
    };

    issue(0);
    issue(1);

    int s = 0;
    for (int kt = 0; kt < KT; kt++) {
        if (kt + 1 < KT) asm volatile("cp.async.wait_group 1;" ::: "memory");
        else             asm volatile("cp.async.wait_group 0;" ::: "memory");
        __syncthreads();
        if (kt + 2 < KT) {
            int ns = s + 2; if (ns >= 3) ns -= 3;
            issue(ns);
        }
        const uint32_t* As32 = (const uint32_t*)(smc + s * 32768);
        const uint32_t* Bs32 = As32 + 4096;

        #pragma unroll
        for (int ks = 0; ks < 4; ks++) {
            const int c0 = (((2 * ks) ^ g) << 2) | t4;
            const int c1 = (((2 * ks + 1) ^ g) << 2) | t4;
            uint32_t af[2][4];
            #pragma unroll
            for (int mi = 0; mi < 2; mi++) {
                const int r = ((wm << 5) + (mi << 4) + g) << 5;
                af[mi][0] = As32[r + c0];
                af[mi][1] = As32[r + 256 + c0];
                af[mi][2] = As32[r + c1];
                af[mi][3] = As32[r + 256 + c1];
            }
            #pragma unroll
            for (int ni = 0; ni < 8; ni++) {
                const int rn = ((wn << 6) + (ni << 3) + g) << 5;
                uint32_t bf[2] = { Bs32[rn + c0], Bs32[rn + c1] };
                mma16(acc[0][ni], af[0], bf);
                mma16(acc[1][ni], af[1], bf);
            }
        }
        if (++s == 3) s = 0;
    }

    // epilogue
    #pragma unroll
    for (int mi = 0; mi < 2; mi++) {
        const int row0 = bm + (wm << 5) + (mi << 4) + g;
        #pragma unroll
        for (int ni = 0; ni < 8; ni++) {
            const int lcol = bn + (wn << 6) + (ni << 3) + (t4 << 1);
            const float b0 = bias[lcol], b1 = bias[lcol + 1];
            float v00 = acc[mi][ni][0] + b0, v01 = acc[mi][ni][1] + b1;
            float v10 = acc[mi][ni][2] + b0, v11 = acc[mi][ni][3] + b1;
            const size_t i0 = (size_t)row0 * N + lcol;
            const size_t i1 = i0 + (size_t)8 * N;
            if (HASRES) {
                v00 += res[i0]; v01 += res[i0 + 1];
                v10 += res[i1]; v11 += res[i1 + 1];
            }
            if (ACT == 1) {
                v00 = gelu_f(v00); v01 = gelu_f(v01);
                v10 = gelu_f(v10); v11 = gelu_f(v11);
            }
            if (OUTH) {
                *(__half2*)&Ch[i0] =
                    __halves2half2(__float2half_rn(v00), __float2half_rn(v01));
                *(__half2*)&Ch[i1] =
                    __halves2half2(__float2half_rn(v10), __float2half_rn(v11));
            } else {
                *(float2*)&Cf[i0] = make_float2(v00, v01);
                *(float2*)&Cf[i1] = make_float2(v10, v11);
            }
        }
    }
}

// ---------------- FP16 causal flash attention ------------------------------
// q-tile 128, seq-tile 64, 512 thr. Q/K/V half (272B rows), S fp32, P half.
// bytes: Qs@0 34816 | Ks@34816 17408 | Vs@52224 17408 | Ss(f32)@69632 34816 |
//        Ps@104448 18432 | m@122880 l@123392 a@123904 | total 124416
#define FSMEM 124416

__global__ __launch_bounds__(512, 1) void flash_kernel(
    const __half* __restrict__ QKV, __half* __restrict__ O)
{
    extern __shared__ char smc[];
    const uint32_t vbase = smem_u32(smc) + 52224u;
    float* Ssf  = (float*)(smc + 69632);
    __half* Psh = (__half*)(smc + 104448);
    float* mrow = (float*)(smc + 122880);
    float* lrow = (float*)(smc + 123392);
    float* arow = (float*)(smc + 123904);
    const uint32_t* Qs32 = (const uint32_t*)smc;
    const uint32_t* Ks32 = (const uint32_t*)(smc + 34816);
    const uint32_t* Ps32 = (const uint32_t*)(smc + 104448);

    const int tid = threadIdx.x;
    const int warp = tid >> 5, lane = tid & 31;
    const int g = lane >> 2, t4 = lane & 3;
    const int qb = warp >> 2, w4 = warp & 3;
    const int b = blockIdx.y >> 4, h = blockIdx.y & 15;
    const int qi = (int)gridDim.x - 1 - (int)blockIdx.x;
    const int q0 = qi << 7;
    const size_t qbase = (size_t)b * 2048 * 6144 + (size_t)h * 128;
    const __half* Qg = QKV + qbase;
    const __half* Kg = QKV + qbase + 2048;
    const __half* Vg = QKV + qbase + 4096;
    __half*       Og = O + ((size_t)b * 2048) * 2048 + (size_t)h * 128;

    // load Q tile: 128 rows x 256B into 272B rows
    #pragma unroll
    for (int rr = 0; rr < 4; rr++) {
        const int c = tid + (rr << 9);
        const int row = c >> 4, chk = c & 15;
        *(uint4*)(smc + row * 272 + chk * 16) =
            *(const uint4*)(Qg + (size_t)(q0 + row) * 6144 + chk * 8);
    }
    if (tid < 128) { mrow[tid] = -1e30f; lrow[tid] = 0.f; }

    float o[2][4][4];
    #pragma unroll
    for (int mi = 0; mi < 2; mi++)
        #pragma unroll
        for (int ni = 0; ni < 4; ni++)
            #pragma unroll
            for (int c = 0; c < 4; c++) o[mi][ni][c] = 0.f;

    const int ntile = (qi << 1) + 2;
    for (int kt = 0; kt < ntile; kt++) {
        const int k0 = kt << 6;
        __syncthreads();
        #pragma unroll
        for (int rr = 0; rr < 2; rr++) {
            const int c = tid + (rr << 9);
            const int row = c >> 4, chk = c & 15;
            *(uint4*)(smc + 34816 + row * 272 + chk * 16) =
                *(const uint4*)(Kg + (size_t)(k0 + row) * 6144 + chk * 8);
            *(uint4*)(smc + 52224 + row * 272 + chk * 16) =
                *(const uint4*)(Vg + (size_t)(k0 + row) * 6144 + chk * 8);
        }
        __syncthreads();

        // S[128,64] = Q K^T ; warp: 32q x 16n ; DH=128 -> 8 ks
        {
            float sacc[2][2][4];
            #pragma unroll
            for (int mi = 0; mi < 2; mi++)
                #pragma unroll
                for (int ni = 0; ni < 2; ni++)
                    #pragma unroll
                    for (int c = 0; c < 4; c++) sacc[mi][ni][c] = 0.f;
            const int m0 = qb << 5, nb = w4 << 4;
            #pragma unroll
            for (int ks = 0; ks < 8; ks++) {
                const int u0 = (ks << 3) + t4, u1 = u0 + 4;
                uint32_t af[2][4];
                #pragma unroll
                for (int mi = 0; mi < 2; mi++) {
                    const int r = (m0 + (mi << 4) + g) * 68;
                    af[mi][0] = Qs32[r + u0];
                    af[mi][1] = Qs32[r + 544 + u0];
                    af[mi][2] = Qs32[r + u1];
                    af[mi][3] = Qs32[r + 544 + u1];
                }
                #pragma unroll
                for (int ni = 0; ni < 2; ni++) {
                    const int rn = (nb + (ni << 3) + g) * 68;
                    uint32_t bf[2] = { Ks32[rn + u0], Ks32[rn + u1] };
                    mma16(sacc[0][ni], af[0], bf);
                    mma16(sacc[1][ni], af[1], bf);
                }
            }
            #pragma unroll
            for (int mi = 0; mi < 2; mi++) {
                const int r0 = m0 + (mi << 4) + g, r1 = r0 + 8;
                #pragma unroll
                for (int ni = 0; ni < 2; ni++) {
                    const int col = nb + (ni << 3) + (t4 << 1);
                    float v00 = sacc[mi][ni][0] * 0.08838834764831845f;
                    float v01 = sacc[mi][ni][1] * 0.08838834764831845f;
                    float v10 = sacc[mi][ni][2] * 0.08838834764831845f;
                    float v11 = sacc[mi][ni][3] * 0.08838834764831845f;
                    if (k0 + col     > q0 + r0) v00 = -1e30f;
                    if (k0 + col + 1 > q0 + r0) v01 = -1e30f;
                    if (k0 + col     > q0 + r1) v10 = -1e30f;
                    if (k0 + col + 1 > q0 + r1) v11 = -1e30f;
                    Ssf[r0 * 68 + col] = v00; Ssf[r0 * 68 + col + 1] = v01;
                    Ssf[r1 * 68 + col] = v10; Ssf[r1 * 68 + col + 1] = v11;
                }
            }
        }
        __syncthreads();

        // online softmax: 128 rows, 4 thr/row; P half into Ps
        {
            const int rid = tid >> 2, c0 = tid & 3;
            float mx = -1e30f;
            #pragma unroll
            for (int jc = c0; jc < 64; jc += 4) mx = fmaxf(mx, Ssf[rid * 68 + jc]);
            mx = fmaxf(mx, __shfl_xor_sync(0xffffffffu, mx, 1));
            mx = fmaxf(mx, __shfl_xor_sync(0xffffffffu, mx, 2));
            const float mold = mrow[rid];
            const float mnew = fmaxf(mold, mx);
            float sum = 0.f;
            #pragma unroll
            for (int jc = c0; jc < 64; jc += 4) {
                const __half ph = __float2half_rn(fexp(Ssf[rid * 68 + jc] - mnew));
                Psh[rid * 72 + jc] = ph;
                sum += __half2float(ph);
            }
            sum += __shfl_xor_sync(0xffffffffu, sum, 1);
            sum += __shfl_xor_sync(0xffffffffu, sum, 2);
            if (c0 == 0) {
                arow[rid] = fexp(mold - mnew);
                lrow[rid] = lrow[rid] * arow[rid] + sum;
                mrow[rid] = mnew;
            }
        }
        __syncthreads();

        // O[128q,128d] += P V ; warp: 32q x 32d ; seq 64 -> 4 ks
        {
            const int qw = qb << 5, db = w4 << 5;
            #pragma unroll
            for (int mi = 0; mi < 2; mi++) {
                const int qr = qw + (mi << 4) + g;
                const float a0 = arow[qr], a1 = arow[qr + 8];
                #pragma unroll
                for (int ni = 0; ni < 4; ni++) {
                    o[mi][ni][0] *= a0; o[mi][ni][1] *= a0;
                    o[mi][ni][2] *= a1; o[mi][ni][3] *= a1;
                }
            }
            #pragma unroll
            for (int ks = 0; ks < 4; ks++) {
                const int u0 = (ks << 3) + t4, u1 = u0 + 4;
                uint32_t af[2][4];
                #pragma unroll
                for (int mi = 0; mi < 2; mi++) {
                    const int r = (qw + (mi << 4) + g) * 36;
                    af[mi][0] = Ps32[r + u0];
                    af[mi][1] = Ps32[r + 288 + u0];
                    af[mi][2] = Ps32[r + u1];
                    af[mi][3] = Ps32[r + 288 + u1];
                }
                #pragma unroll
                for (int ni = 0; ni < 4; ni++) {
                    uint32_t bv0, bv1;
                    const uint32_t vad = vbase +
                        (uint32_t)(((ks << 4) + (lane & 15)) * 272 + (db + (ni << 3)) * 2);
                    asm volatile(
                        "ldmatrix.sync.aligned.m8n8.x2.trans.shared.b16 {%0,%1}, [%2];"
                        : "=r"(bv0), "=r"(bv1) : "r"(vad));
                    uint32_t bf[2] = { bv0, bv1 };
                    mma16(o[0][ni], af[0], bf);
                    mma16(o[1][ni], af[1], bf);
                }
            }
        }
    }

    // normalize + store O half
    __syncthreads();
    {
        const int qw = qb << 5, db = w4 << 5;
        #pragma unroll
        for (int mi = 0; mi < 2; mi++) {
            const int qr = qw + (mi << 4) + g;
            const float inv0 = 1.0f / lrow[qr], inv1 = 1.0f / lrow[qr + 8];
            #pragma unroll
            for (int ni = 0; ni < 4; ni++) {
                const int dc = db + (ni << 3) + (t4 << 1);
                *(__half2*)&Og[(size_t)(q0 + qr) * 2048 + dc] =
                    __halves2half2(__float2half_rn(o[mi][ni][0] * inv0),
                                   __float2half_rn(o[mi][ni][1] * inv0));
                *(__half2*)&Og[(size_t)(q0 + qr + 8) * 2048 + dc] =
                    __halves2half2(__float2half_rn(o[mi][ni][2] * inv1),
                                   __float2half_rn(o[mi][ni][3] * inv1));
            }
        }
    }
}

// ---------------- host orchestration ---------------------------------------
extern "C" void kernel_launch(void* const* d_in, const int* in_sizes, int n_in,
                              void* d_out, int out_size)
{
    const float* x     = (const float*)d_in[0];
    const float* ln1_g = (const float*)d_in[2];
    const float* ln1_b = (const float*)d_in[3];
    const float* wq    = (const float*)d_in[4];
    const float* bq    = (const float*)d_in[5];
    const float* wk    = (const float*)d_in[6];
    const float* bk    = (const float*)d_in[7];
    const float* wv    = (const float*)d_in[8];
    const float* bv    = (const float*)d_in[9];
    const float* wo    = (const float*)d_in[10];
    const float* bo    = (const float*)d_in[11];
    const float* ln2_g = (const float*)d_in[12];
    const float* ln2_b = (const float*)d_in[13];
    const float* w_in  = (const float*)d_in[14];
    const float* b_in  = (const float*)d_in[15];
    const float* w_out = (const float*)d_in[16];
    const float* b_out = (const float*)d_in[17];
    float* out = (float*)d_out;

    float *x1, *bqkv;
    __half *xn, *qkv, *attn, *h, *wqkvt, *wot, *wint, *woutt;
    cudaGetSymbolAddress((void**)&x1,    g_x1);
    cudaGetSymbolAddress((void**)&bqkv,  g_bqkv);
    cudaGetSymbolAddress((void**)&xn,    g_xn);
    cudaGetSymbolAddress((void**)&qkv,   g_qkv);
    cudaGetSymbolAddress((void**)&attn,  g_attn);
    cudaGetSymbolAddress((void**)&h,     g_h);
    cudaGetSymbolAddress((void**)&wqkvt, g_wqkvt);
    cudaGetSymbolAddress((void**)&wot,   g_wot);
    cudaGetSymbolAddress((void**)&wint,  g_wint);
    cudaGetSymbolAddress((void**)&woutt, g_woutt);

    cudaFuncSetAttribute(flash_kernel,
                         cudaFuncAttributeMaxDynamicSharedMemorySize, FSMEM);
    cudaFuncSetAttribute(gemm_cp<0,0,1>,
                         cudaFuncAttributeMaxDynamicSharedMemorySize, GSMEM);
    cudaFuncSetAttribute(gemm_cp<0,1,0>,
                         cudaFuncAttributeMaxDynamicSharedMemorySize, GSMEM);
    cudaFuncSetAttribute(gemm_cp<1,0,1>,
                         cudaFuncAttributeMaxDynamicSharedMemorySize, GSMEM);

    prep_a<<<12312, 256>>>(wq, wk, wv, bq, bk, bv);
    prep_b<<<36864, 256>>>(wo, w_in, w_out);
    ln_kernel<<<4096, 256>>>(x, ln1_g, ln1_b, xn);
    gemm_cp<0,0,1><<<dim3(48, 32), 256, GSMEM>>>(                      // QKV
        xn, wqkvt, bqkv, nullptr, nullptr, qkv, 4096, 6144, 2048);
    flash_kernel<<<dim3(16, 32), 512, FSMEM>>>(qkv, attn);
    gemm_cp<0,1,0><<<dim3(16, 32), 256, GSMEM>>>(                      // O-proj
        attn, wot, bo, x, x1, nullptr, 4096, 2048, 2048);
    ln_kernel<<<4096, 256>>>(x1, ln2_g, ln2_b, xn);
    gemm_cp<1,0,1><<<dim3(64, 32), 256, GSMEM>>>(                      // MLP in
        xn, wint, b_in, nullptr, nullptr, h, 4096, 8192, 2048);
    gemm_cp<0,1,0><<<dim3(16, 32), 256, GSMEM>>>(                      // MLP out
        h, woutt, b_out, x1, out, nullptr, 4096, 2048, 8192);
}